// round 11
// baseline (speedup 1.0000x reference)
#include <cuda_runtime.h>
#include <cuda_bf16.h>
#include <cuda_fp8.h>
#include <cstdint>

// Problem constants (fixed: B=4096, P=4, D=768)
#define BQ     4096
#define PP     4
#define DD     768
#define NKEYS  (BQ + BQ * PP)          // 20480 keys: [queries | docs]
#define TILE_M 128
#define TILE_N 256
#define KS     64                      // K per pipeline stage (64 fp8 = 64B rows)
#define NSTAGES (DD / KS)              // 12
#define NPIPE  3                       // cp.async pipeline depth
#define NTILES (NKEYS / TILE_N)        // 80
#define MTILES (BQ / TILE_M)           // 32

// Dynamic smem: 3 stages x (A 8KB + B 16KB) + reduction buffer 2KB
#define STAGE_BYTES 24576
#define SMEM_A(s)   ((s) * STAGE_BYTES)
#define SMEM_B(s)   ((s) * STAGE_BYTES + 8192)
#define SMEM_RED    (NPIPE * STAGE_BYTES)            // float[4][128]
#define SMEM_TOTAL  (NPIPE * STAGE_BYTES + 2048)     // 75776

// Scratch (__device__ globals: allocation-free rule)
__device__ uint8_t g_keys[(size_t)NKEYS * DD];       // normalized keys, e4m3
__device__ float g_partial[NTILES * BQ];
__device__ float g_sim_a[BQ * PP];
__device__ float g_bsum[16];

// ---------------- PTX helpers (legal on plain sm_100) ----------------
__device__ __forceinline__ uint32_t smem_u32(const void* p) {
    uint32_t a;
    asm("{ .reg .u64 t; cvta.to.shared.u64 t, %1; cvt.u32.u64 %0, t; }" : "=r"(a) : "l"(p));
    return a;
}
__device__ __forceinline__ void cp_async16(uint32_t dst, const void* src) {
    asm volatile("cp.async.cg.shared.global [%0], [%1], 16;" :: "r"(dst), "l"(src));
}
#define CP_COMMIT() asm volatile("cp.async.commit_group;" ::: "memory")
#define CP_WAIT1()  asm volatile("cp.async.wait_group 1;" ::: "memory")

__device__ __forceinline__ void ldsm_x4(uint32_t& r0, uint32_t& r1, uint32_t& r2,
                                        uint32_t& r3, uint32_t addr) {
    asm volatile("ldmatrix.sync.aligned.m8n8.x4.shared.b16 {%0,%1,%2,%3}, [%4];"
                 : "=r"(r0), "=r"(r1), "=r"(r2), "=r"(r3) : "r"(addr));
}
// FP8 e4m3 MMA, k=32, fp32 accum.
__device__ __forceinline__ void mma16832_fp8(float& c0, float& c1, float& c2, float& c3,
                                             uint32_t a0, uint32_t a1, uint32_t a2, uint32_t a3,
                                             uint32_t b0, uint32_t b1) {
    asm volatile(
        "mma.sync.aligned.m16n8k32.row.col.f32.e4m3.e4m3.f32 "
        "{%0,%1,%2,%3}, {%4,%5,%6,%7}, {%8,%9}, {%0,%1,%2,%3};"
        : "+f"(c0), "+f"(c1), "+f"(c2), "+f"(c3)
        : "r"(a0), "r"(a1), "r"(a2), "r"(a3), "r"(b0), "r"(b1));
}

// 64B-row swizzle: 16B chunk c of row r -> slot c ^ ((r>>1)&3). Conflict-free
// for cp.async stores and every ldmatrix phase (validated R4-R10).
__device__ __forceinline__ uint32_t sw_off(uint32_t row, uint32_t c16) {
    return row * 64u + ((c16 ^ ((row >> 1) & 3u)) << 4);
}

// ---------------------------------------------------------------------------
// 1) L2-normalize all rows -> e4m3 g_keys
// ---------------------------------------------------------------------------
__global__ void __launch_bounds__(256) normalize_kernel(const float* __restrict__ q,
                                                        const float* __restrict__ d) {
    const int r = blockIdx.x;
    const float* src = (r < BQ) ? (q + (size_t)r * DD) : (d + (size_t)(r - BQ) * DD);
    __shared__ float sh[256];
    const int t = threadIdx.x;

    float4 v = make_float4(0.f, 0.f, 0.f, 0.f);
    float ss = 0.f;
    if (t < DD / 4) {
        v = ((const float4*)src)[t];
        ss = v.x * v.x + v.y * v.y + v.z * v.z + v.w * v.w;
    }
    sh[t] = ss; __syncthreads();
    #pragma unroll
    for (int s = 128; s > 0; s >>= 1) { if (t < s) sh[t] += sh[t + s]; __syncthreads(); }
    if (t < DD / 4) {
        float rn = 1.0f / fmaxf(sqrtf(sh[0]), 1e-12f);
        uint32_t o = 0;
        o |= (uint32_t)__nv_cvt_float_to_fp8(v.x * rn, __NV_SATFINITE, __NV_E4M3);
        o |= (uint32_t)__nv_cvt_float_to_fp8(v.y * rn, __NV_SATFINITE, __NV_E4M3) << 8;
        o |= (uint32_t)__nv_cvt_float_to_fp8(v.z * rn, __NV_SATFINITE, __NV_E4M3) << 16;
        o |= (uint32_t)__nv_cvt_float_to_fp8(v.w * rn, __NV_SATFINITE, __NV_E4M3) << 24;
        *(uint32_t*)&g_keys[(size_t)r * DD + t * 4] = o;
    }
}

// ---------------------------------------------------------------------------
// 2) FP8 MMA GEMM + exp + rowsum. 128x256 tile, 8 warps (2x4), warp 64x64.
//    Query-query diagonal contributes exactly zero (replaces "- exp(1/t)").
// ---------------------------------------------------------------------------
__device__ __forceinline__ void load_stage(uint32_t smem_base, int buf, int kt,
                                           int m0, int n0, int tid) {
    const uint32_t a_base = smem_base + SMEM_A(buf);
    const uint32_t b_base = smem_base + SMEM_B(buf);
    #pragma unroll
    for (int i = 0; i < 6; i++) {
        const int idx = tid + i * 256;          // 0..1535
        const int row = idx >> 2;               // 0..383 (0-127: A, 128-383: B)
        const int c   = idx & 3;                // 16B chunk within 64B row
        uint32_t dst;
        int gr;
        if (row < TILE_M) { gr = m0 + row;            dst = a_base + sw_off(row, c); }
        else              { gr = n0 + (row - TILE_M); dst = b_base + sw_off(row - TILE_M, c); }
        cp_async16(dst, g_keys + (size_t)gr * DD + kt + c * 16);
    }
}

__global__ void __launch_bounds__(256, 1) gemm_exp_kernel() {
    extern __shared__ char smem[];
    const uint32_t smem_base = smem_u32(smem);
    const int tid  = threadIdx.x;
    const int lane = tid & 31;
    const int wid  = tid >> 5;
    const int wm   = (wid & 1) * 64;         // warp M offset (2 rows of warps)
    const int wn   = (wid >> 1) * 64;        // warp N offset (4 cols of warps)
    const int ntile = blockIdx.x;            // 0..79
    const int mtile = blockIdx.y;            // 0..31
    const int m0 = mtile * TILE_M;
    const int n0 = ntile * TILE_N;

    float acc[4][8][4];                       // [mi][ni][c0..c3]
    #pragma unroll
    for (int i = 0; i < 4; i++)
        #pragma unroll
        for (int j = 0; j < 8; j++)
            #pragma unroll
            for (int c = 0; c < 4; c++) acc[i][j][c] = 0.f;

    // Prologue: 2 stages in flight
    load_stage(smem_base, 0, 0, m0, n0, tid);  CP_COMMIT();
    load_stage(smem_base, 1, KS, m0, n0, tid); CP_COMMIT();

    const int lr = lane & 15;                // ldmatrix row-within-16
    const int lc = lane >> 4;                // ldmatrix 16B half select

    for (int s = 0; s < NSTAGES; s++) {
        const int buf = s % NPIPE;
        CP_WAIT1();                           // stage s data resident
        __syncthreads();                      // all warps done with buf (s-1)

        if (s + 2 < NSTAGES) load_stage(smem_base, (s + 2) % NPIPE, (s + 2) * KS, m0, n0, tid);
        CP_COMMIT();

        const uint32_t a_base = smem_base + SMEM_A(buf);
        const uint32_t b_base = smem_base + SMEM_B(buf);

        #pragma unroll
        for (int ks = 0; ks < 2; ks++) {      // two k32 steps per 64-K stage
            const uint32_t c16 = ks * 2 + lc; // 16B chunk: k-halves 0-15 / 16-31
            uint32_t a[4][4];
            #pragma unroll
            for (int mi = 0; mi < 4; mi++) {
                const uint32_t row = wm + mi * 16 + lr;
                ldsm_x4(a[mi][0], a[mi][1], a[mi][2], a[mi][3], a_base + sw_off(row, c16));
            }
            uint32_t b[8][2];
            #pragma unroll
            for (int bp = 0; bp < 4; bp++) {  // each ldmatrix.x4 covers 16 n-rows
                const uint32_t row = wn + bp * 16 + lr;
                uint32_t q0, q1, q2, q3;
                ldsm_x4(q0, q1, q2, q3, b_base + sw_off(row, c16));
                b[bp * 2 + 0][0] = q0; b[bp * 2 + 0][1] = q2;   // n 0-7: k0-15, k16-31
                b[bp * 2 + 1][0] = q1; b[bp * 2 + 1][1] = q3;   // n 8-15
            }
            #pragma unroll
            for (int mi = 0; mi < 4; mi++)
                #pragma unroll
                for (int ni = 0; ni < 8; ni++)
                    mma16832_fp8(acc[mi][ni][0], acc[mi][ni][1], acc[mi][ni][2], acc[mi][ni][3],
                                 a[mi][0], a[mi][1], a[mi][2], a[mi][3], b[ni][0], b[ni][1]);
        }
        __syncthreads();
    }

    // ---- Epilogue: exp, row sums (diagonal excluded), diagonal scatter ----
    const float INVT = (float)(1.0 / 0.07);
    float rs[4][2];                           // [mi][half: row / row+8]
    #pragma unroll
    for (int mi = 0; mi < 4; mi++) { rs[mi][0] = 0.f; rs[mi][1] = 0.f; }

    const int qr = lane >> 2;                 // quad row 0..7
    const int qc = (lane & 3) * 2;            // quad col base
    #pragma unroll
    for (int mi = 0; mi < 4; mi++) {
        const int r_lo = m0 + wm + mi * 16 + qr;
        const int r_hi = r_lo + 8;
        #pragma unroll
        for (int ni = 0; ni < 8; ni++) {
            const int cg = n0 + wn + ni * 8 + qc;   // global col of c0/c2
            float e0 = __expf(acc[mi][ni][0] * INVT);
            float e1 = __expf(acc[mi][ni][1] * INVT);
            float e2 = __expf(acc[mi][ni][2] * INVT);
            float e3 = __expf(acc[mi][ni][3] * INVT);
            // exclude query-query self-similarity (cg==row implies cg < BQ)
            if (cg     == r_lo) e0 = 0.f;
            if (cg + 1 == r_lo) e1 = 0.f;
            if (cg     == r_hi) e2 = 0.f;
            if (cg + 1 == r_hi) e3 = 0.f;
            rs[mi][0] += e0 + e1;
            rs[mi][1] += e2 + e3;
            const int kd0 = cg - BQ, kd1 = cg + 1 - BQ;
            if (kd0 >= 0 && (kd0 >> 2) == r_lo) g_sim_a[kd0] = e0;
            if (kd1 >= 0 && (kd1 >> 2) == r_lo) g_sim_a[kd1] = e1;
            if (kd0 >= 0 && (kd0 >> 2) == r_hi) g_sim_a[kd0] = e2;
            if (kd1 >= 0 && (kd1 >> 2) == r_hi) g_sim_a[kd1] = e3;
        }
    }
    // reduce across the 4 lanes of each quad-row
    #pragma unroll
    for (int mi = 0; mi < 4; mi++)
        #pragma unroll
        for (int h = 0; h < 2; h++) {
            rs[mi][h] += __shfl_xor_sync(0xffffffffu, rs[mi][h], 1);
            rs[mi][h] += __shfl_xor_sync(0xffffffffu, rs[mi][h], 2);
        }

    float* red = (float*)(smem + SMEM_RED);   // [4 warp_n][128 rows]
    __syncthreads();                          // stage buffers no longer needed
    if ((lane & 3) == 0) {
        const int wncol = wid >> 1;
        #pragma unroll
        for (int mi = 0; mi < 4; mi++)
            #pragma unroll
            for (int h = 0; h < 2; h++)
                red[wncol * 128 + wm + mi * 16 + h * 8 + qr] = rs[mi][h];
    }
    __syncthreads();
    if (tid < 128) {
        float s = red[tid] + red[128 + tid] + red[256 + tid] + red[384 + tid];
        g_partial[ntile * BQ + m0 + tid] = s;
    }
}

// ---------------------------------------------------------------------------
// 3) Fused rowsum + log-loss partials. 16 blocks x 256 threads, 1 row/thread.
// ---------------------------------------------------------------------------
__global__ void __launch_bounds__(256) loss_partial_kernel() {
    __shared__ float sh[256];
    const int tid = threadIdx.x;
    const int i = blockIdx.x * 256 + tid;     // 0..4095
    float s = 0.f;
    #pragma unroll 4
    for (int t = 0; t < NTILES; t++) s += g_partial[t * BQ + i];
    const float a0 = g_sim_a[4 * i + 0];
    const float a1 = g_sim_a[4 * i + 1];
    const float a2 = g_sim_a[4 * i + 2];
    const float a3 = g_sim_a[4 * i + 3];
    const float R = s - (a0 + a1 + a2 + a3);  // rowsum already excludes self term
    float local = (logf(R + a0) - logf(a0)) + (logf(R + a1) - logf(a1))
                + (logf(R + a2) - logf(a2)) + (logf(R + a3) - logf(a3));
    sh[tid] = local; __syncthreads();
    #pragma unroll
    for (int s2 = 128; s2 > 0; s2 >>= 1) { if (tid < s2) sh[tid] += sh[tid + s2]; __syncthreads(); }
    if (tid == 0) g_bsum[blockIdx.x] = sh[0];
}

__global__ void loss_final_kernel(float* __restrict__ out) {
    if (threadIdx.x == 0) {
        float s = 0.f;
        #pragma unroll
        for (int b = 0; b < 16; b++) s += g_bsum[b];
        out[0] = s * (1.0f / (float)(BQ * PP));
    }
}

// ---------------------------------------------------------------------------
extern "C" void kernel_launch(void* const* d_in, const int* in_sizes, int n_in,
                              void* d_out, int out_size) {
    const float* q = (const float*)d_in[0];   // [4096, 768]
    const float* d = (const float*)d_in[1];   // [16384, 768]
    float* out = (float*)d_out;

    cudaFuncSetAttribute(gemm_exp_kernel,
                         cudaFuncAttributeMaxDynamicSharedMemorySize, SMEM_TOTAL);

    normalize_kernel<<<NKEYS, 256>>>(q, d);
    gemm_exp_kernel<<<dim3(NTILES, MTILES), 256, SMEM_TOTAL>>>();
    loss_partial_kernel<<<16, 256>>>();
    loss_final_kernel<<<1, 32>>>(out);
}

// round 12
// speedup vs baseline: 1.1244x; 1.1244x over previous
#include <cuda_runtime.h>
#include <cuda_bf16.h>
#include <cuda_fp8.h>
#include <cstdint>

// Problem constants (fixed: B=4096, P=4, D=768)
#define BQ     4096
#define PP     4
#define DD     768
#define NKEYS  (BQ + BQ * PP)          // 20480 keys: [queries | docs]
#define TILE_M 128
#define TILE_N 128
#define KS     64                      // K per pipeline stage (64 fp8 = 64B rows)
#define NSTAGES (DD / KS)              // 12
#define NPIPE  4                       // cp.async pipeline depth
#define NTILES (NKEYS / TILE_N)        // 160
#define MTILES (BQ / TILE_M)           // 32

// Dynamic smem: 4 stages x (A 8KB + B 8KB) + reduction buffer 2KB
#define STAGE_BYTES 16384
#define SMEM_A(s)   ((s) * STAGE_BYTES)
#define SMEM_B(s)   ((s) * STAGE_BYTES + 8192)
#define SMEM_RED    (NPIPE * STAGE_BYTES)            // float[4][128]
#define SMEM_TOTAL  (NPIPE * STAGE_BYTES + 2048)     // 67584 -> occ 2

// Scratch (__device__ globals: allocation-free rule)
__device__ uint8_t g_keys[(size_t)NKEYS * DD];       // normalized keys, e4m3
__device__ float g_partial[NTILES * BQ];
__device__ float g_sim_a[BQ * PP];
__device__ float g_bsum[16];

// ---------------- PTX helpers (legal on plain sm_100) ----------------
__device__ __forceinline__ uint32_t smem_u32(const void* p) {
    uint32_t a;
    asm("{ .reg .u64 t; cvta.to.shared.u64 t, %1; cvt.u32.u64 %0, t; }" : "=r"(a) : "l"(p));
    return a;
}
__device__ __forceinline__ void cp_async16(uint32_t dst, const void* src) {
    asm volatile("cp.async.cg.shared.global [%0], [%1], 16;" :: "r"(dst), "l"(src));
}
#define CP_COMMIT() asm volatile("cp.async.commit_group;" ::: "memory")
#define CP_WAIT2()  asm volatile("cp.async.wait_group 2;" ::: "memory")

__device__ __forceinline__ void ldsm_x4(uint32_t& r0, uint32_t& r1, uint32_t& r2,
                                        uint32_t& r3, uint32_t addr) {
    asm volatile("ldmatrix.sync.aligned.m8n8.x4.shared.b16 {%0,%1,%2,%3}, [%4];"
                 : "=r"(r0), "=r"(r1), "=r"(r2), "=r"(r3) : "r"(addr));
}
// FP8 e4m3 MMA, k=32, fp32 accum.
__device__ __forceinline__ void mma16832_fp8(float& c0, float& c1, float& c2, float& c3,
                                             uint32_t a0, uint32_t a1, uint32_t a2, uint32_t a3,
                                             uint32_t b0, uint32_t b1) {
    asm volatile(
        "mma.sync.aligned.m16n8k32.row.col.f32.e4m3.e4m3.f32 "
        "{%0,%1,%2,%3}, {%4,%5,%6,%7}, {%8,%9}, {%0,%1,%2,%3};"
        : "+f"(c0), "+f"(c1), "+f"(c2), "+f"(c3)
        : "r"(a0), "r"(a1), "r"(a2), "r"(a3), "r"(b0), "r"(b1));
}

// 64B-row swizzle: 16B chunk c of row r -> slot c ^ ((r>>1)&3). Conflict-free
// for cp.async stores and every ldmatrix phase (validated R4-R11).
__device__ __forceinline__ uint32_t sw_off(uint32_t row, uint32_t c16) {
    return row * 64u + ((c16 ^ ((row >> 1) & 3u)) << 4);
}

// ---------------------------------------------------------------------------
// 1) L2-normalize all rows -> e4m3 g_keys
// ---------------------------------------------------------------------------
__global__ void __launch_bounds__(256) normalize_kernel(const float* __restrict__ q,
                                                        const float* __restrict__ d) {
    const int r = blockIdx.x;
    const float* src = (r < BQ) ? (q + (size_t)r * DD) : (d + (size_t)(r - BQ) * DD);
    __shared__ float sh[256];
    const int t = threadIdx.x;

    float4 v = make_float4(0.f, 0.f, 0.f, 0.f);
    float ss = 0.f;
    if (t < DD / 4) {
        v = ((const float4*)src)[t];
        ss = v.x * v.x + v.y * v.y + v.z * v.z + v.w * v.w;
    }
    sh[t] = ss; __syncthreads();
    #pragma unroll
    for (int s = 128; s > 0; s >>= 1) { if (t < s) sh[t] += sh[t + s]; __syncthreads(); }
    if (t < DD / 4) {
        float rn = 1.0f / fmaxf(sqrtf(sh[0]), 1e-12f);
        uint32_t o = 0;
        o |= (uint32_t)__nv_cvt_float_to_fp8(v.x * rn, __NV_SATFINITE, __NV_E4M3);
        o |= (uint32_t)__nv_cvt_float_to_fp8(v.y * rn, __NV_SATFINITE, __NV_E4M3) << 8;
        o |= (uint32_t)__nv_cvt_float_to_fp8(v.z * rn, __NV_SATFINITE, __NV_E4M3) << 16;
        o |= (uint32_t)__nv_cvt_float_to_fp8(v.w * rn, __NV_SATFINITE, __NV_E4M3) << 24;
        *(uint32_t*)&g_keys[(size_t)r * DD + t * 4] = o;
    }
}

// ---------------------------------------------------------------------------
// 2) FP8 MMA GEMM + exp + rowsum. 128x128 tile, 8 warps (2x4), warp 64x32.
//    NPIPE=4 + single barrier per stage: the buffer loaded at stage s
//    ((s+3)%4) is the one all warps finished computing at stage s-1, which
//    the top-of-stage-s barrier already orders.
//    Query-query diagonal contributes exactly zero (replaces "- exp(1/t)").
// ---------------------------------------------------------------------------
__device__ __forceinline__ void load_stage(uint32_t smem_base, int buf, int kt,
                                           int m0, int n0, int tid) {
    const uint32_t a_base = smem_base + SMEM_A(buf);
    const uint32_t b_base = smem_base + SMEM_B(buf);
    #pragma unroll
    for (int i = 0; i < 4; i++) {
        const int idx = tid + i * 256;          // 0..1023
        const int row = idx >> 2;               // 0..255 (0-127: A, 128-255: B)
        const int c   = idx & 3;                // 16B chunk within 64B row
        uint32_t dst;
        int gr;
        if (row < TILE_M) { gr = m0 + row;            dst = a_base + sw_off(row, c); }
        else              { gr = n0 + (row - TILE_M); dst = b_base + sw_off(row - TILE_M, c); }
        cp_async16(dst, g_keys + (size_t)gr * DD + kt + c * 16);
    }
}

__global__ void __launch_bounds__(256, 2) gemm_exp_kernel() {
    extern __shared__ char smem[];
    const uint32_t smem_base = smem_u32(smem);
    const int tid  = threadIdx.x;
    const int lane = tid & 31;
    const int wid  = tid >> 5;
    const int wm   = (wid & 1) * 64;         // warp M offset (2 rows of warps)
    const int wn   = (wid >> 1) * 32;        // warp N offset (4 cols of warps)
    const int ntile = blockIdx.x;            // 0..159
    const int mtile = blockIdx.y;            // 0..31
    const int m0 = mtile * TILE_M;
    const int n0 = ntile * TILE_N;

    float acc[4][4][4];                       // [mi][ni][c0..c3]
    #pragma unroll
    for (int i = 0; i < 4; i++)
        #pragma unroll
        for (int j = 0; j < 4; j++)
            #pragma unroll
            for (int c = 0; c < 4; c++) acc[i][j][c] = 0.f;

    // Prologue: 3 stages in flight
    load_stage(smem_base, 0, 0, m0, n0, tid);      CP_COMMIT();
    load_stage(smem_base, 1, KS, m0, n0, tid);     CP_COMMIT();
    load_stage(smem_base, 2, 2 * KS, m0, n0, tid); CP_COMMIT();

    const int lr = lane & 15;                // ldmatrix row-within-16
    const int lc = lane >> 4;                // ldmatrix 16B half select

    for (int s = 0; s < NSTAGES; s++) {
        const int buf = s & (NPIPE - 1);
        CP_WAIT2();                           // stage s data resident
        __syncthreads();                      // all warps past compute s-1

        if (s + 3 < NSTAGES) load_stage(smem_base, (s + 3) & (NPIPE - 1),
                                        (s + 3) * KS, m0, n0, tid);
        CP_COMMIT();

        const uint32_t a_base = smem_base + SMEM_A(buf);
        const uint32_t b_base = smem_base + SMEM_B(buf);

        #pragma unroll
        for (int ks = 0; ks < 2; ks++) {      // two k32 steps per 64-K stage
            const uint32_t c16 = ks * 2 + lc; // 16B chunk: k-halves 0-15 / 16-31
            uint32_t a[4][4];
            #pragma unroll
            for (int mi = 0; mi < 4; mi++) {
                const uint32_t row = wm + mi * 16 + lr;
                ldsm_x4(a[mi][0], a[mi][1], a[mi][2], a[mi][3], a_base + sw_off(row, c16));
            }
            uint32_t b[4][2];
            #pragma unroll
            for (int bp = 0; bp < 2; bp++) {  // each ldmatrix.x4 covers 16 n-rows
                const uint32_t row = wn + bp * 16 + lr;
                uint32_t q0, q1, q2, q3;
                ldsm_x4(q0, q1, q2, q3, b_base + sw_off(row, c16));
                b[bp * 2 + 0][0] = q0; b[bp * 2 + 0][1] = q2;   // n 0-7: k0-15, k16-31
                b[bp * 2 + 1][0] = q1; b[bp * 2 + 1][1] = q3;   // n 8-15
            }
            #pragma unroll
            for (int mi = 0; mi < 4; mi++)
                #pragma unroll
                for (int ni = 0; ni < 4; ni++)
                    mma16832_fp8(acc[mi][ni][0], acc[mi][ni][1], acc[mi][ni][2], acc[mi][ni][3],
                                 a[mi][0], a[mi][1], a[mi][2], a[mi][3], b[ni][0], b[ni][1]);
        }
    }

    // ---- Epilogue: exp, row sums (diagonal excluded), diagonal scatter ----
    const float INVT = (float)(1.0 / 0.07);
    float rs[4][2];                           // [mi][half: row / row+8]
    #pragma unroll
    for (int mi = 0; mi < 4; mi++) { rs[mi][0] = 0.f; rs[mi][1] = 0.f; }

    const int qr = lane >> 2;                 // quad row 0..7
    const int qc = (lane & 3) * 2;            // quad col base
    #pragma unroll
    for (int mi = 0; mi < 4; mi++) {
        const int r_lo = m0 + wm + mi * 16 + qr;
        const int r_hi = r_lo + 8;
        #pragma unroll
        for (int ni = 0; ni < 4; ni++) {
            const int cg = n0 + wn + ni * 8 + qc;   // global col of c0/c2
            float e0 = __expf(acc[mi][ni][0] * INVT);
            float e1 = __expf(acc[mi][ni][1] * INVT);
            float e2 = __expf(acc[mi][ni][2] * INVT);
            float e3 = __expf(acc[mi][ni][3] * INVT);
            // exclude query-query self-similarity (cg==row implies cg < BQ)
            if (cg     == r_lo) e0 = 0.f;
            if (cg + 1 == r_lo) e1 = 0.f;
            if (cg     == r_hi) e2 = 0.f;
            if (cg + 1 == r_hi) e3 = 0.f;
            rs[mi][0] += e0 + e1;
            rs[mi][1] += e2 + e3;
            const int kd0 = cg - BQ, kd1 = cg + 1 - BQ;
            if (kd0 >= 0 && (kd0 >> 2) == r_lo) g_sim_a[kd0] = e0;
            if (kd1 >= 0 && (kd1 >> 2) == r_lo) g_sim_a[kd1] = e1;
            if (kd0 >= 0 && (kd0 >> 2) == r_hi) g_sim_a[kd0] = e2;
            if (kd1 >= 0 && (kd1 >> 2) == r_hi) g_sim_a[kd1] = e3;
        }
    }
    // reduce across the 4 lanes of each quad-row
    #pragma unroll
    for (int mi = 0; mi < 4; mi++)
        #pragma unroll
        for (int h = 0; h < 2; h++) {
            rs[mi][h] += __shfl_xor_sync(0xffffffffu, rs[mi][h], 1);
            rs[mi][h] += __shfl_xor_sync(0xffffffffu, rs[mi][h], 2);
        }

    float* red = (float*)(smem + SMEM_RED);   // [4 warp_n][128 rows]
    __syncthreads();                          // stage buffers no longer needed
    if ((lane & 3) == 0) {
        const int wncol = wid >> 1;
        #pragma unroll
        for (int mi = 0; mi < 4; mi++)
            #pragma unroll
            for (int h = 0; h < 2; h++)
                red[wncol * 128 + wm + mi * 16 + h * 8 + qr] = rs[mi][h];
    }
    __syncthreads();
    if (tid < 128) {
        float s = red[tid] + red[128 + tid] + red[256 + tid] + red[384 + tid];
        g_partial[ntile * BQ + m0 + tid] = s;
    }
}

// ---------------------------------------------------------------------------
// 3) Fused rowsum + log-loss partials. 16 blocks x 256 threads, 1 row/thread.
// ---------------------------------------------------------------------------
__global__ void __launch_bounds__(256) loss_partial_kernel() {
    __shared__ float sh[256];
    const int tid = threadIdx.x;
    const int i = blockIdx.x * 256 + tid;     // 0..4095
    float s = 0.f;
    #pragma unroll 4
    for (int t = 0; t < NTILES; t++) s += g_partial[t * BQ + i];
    const float a0 = g_sim_a[4 * i + 0];
    const float a1 = g_sim_a[4 * i + 1];
    const float a2 = g_sim_a[4 * i + 2];
    const float a3 = g_sim_a[4 * i + 3];
    const float R = s - (a0 + a1 + a2 + a3);  // rowsum already excludes self term
    float local = (logf(R + a0) - logf(a0)) + (logf(R + a1) - logf(a1))
                + (logf(R + a2) - logf(a2)) + (logf(R + a3) - logf(a3));
    sh[tid] = local; __syncthreads();
    #pragma unroll
    for (int s2 = 128; s2 > 0; s2 >>= 1) { if (tid < s2) sh[tid] += sh[tid + s2]; __syncthreads(); }
    if (tid == 0) g_bsum[blockIdx.x] = sh[0];
}

__global__ void loss_final_kernel(float* __restrict__ out) {
    if (threadIdx.x == 0) {
        float s = 0.f;
        #pragma unroll
        for (int b = 0; b < 16; b++) s += g_bsum[b];
        out[0] = s * (1.0f / (float)(BQ * PP));
    }
}

// ---------------------------------------------------------------------------
extern "C" void kernel_launch(void* const* d_in, const int* in_sizes, int n_in,
                              void* d_out, int out_size) {
    const float* q = (const float*)d_in[0];   // [4096, 768]
    const float* d = (const float*)d_in[1];   // [16384, 768]
    float* out = (float*)d_out;

    cudaFuncSetAttribute(gemm_exp_kernel,
                         cudaFuncAttributeMaxDynamicSharedMemorySize, SMEM_TOTAL);

    normalize_kernel<<<NKEYS, 256>>>(q, d);
    gemm_exp_kernel<<<dim3(NTILES, MTILES), 256, SMEM_TOTAL>>>();
    loss_partial_kernel<<<16, 256>>>();
    loss_final_kernel<<<1, 32>>>(out);
}

// round 13
// speedup vs baseline: 1.1568x; 1.0288x over previous
#include <cuda_runtime.h>
#include <cuda_bf16.h>
#include <cuda_fp16.h>
#include <cuda_fp8.h>
#include <cstdint>

// Problem constants (fixed: B=4096, P=4, D=768)
#define BQ     4096
#define PP     4
#define DD     768
#define NKEYS  (BQ + BQ * PP)          // 20480 keys: [queries | docs]
#define TILE_M 128
#define TILE_N 128
#define KS     64                      // K per pipeline stage (64 fp8 = 64B rows)
#define NSTAGES (DD / KS)              // 12
#define NPIPE  4                       // cp.async pipeline depth
#define NTILES (NKEYS / TILE_N)        // 160
#define MTILES (BQ / TILE_M)           // 32

// Dynamic smem: 4 stages x (A 8KB + B 8KB) + reduction buffer 2KB
#define STAGE_BYTES 16384
#define SMEM_A(s)   ((s) * STAGE_BYTES)
#define SMEM_B(s)   ((s) * STAGE_BYTES + 8192)
#define SMEM_RED    (NPIPE * STAGE_BYTES)            // float[4][128]
#define SMEM_TOTAL  (NPIPE * STAGE_BYTES + 2048)     // 67584 -> occ 2

// Scratch (__device__ globals: allocation-free rule)
__device__ uint8_t g_keys[(size_t)NKEYS * DD];       // normalized keys, e4m3
__device__ float g_partial[NTILES * BQ];
__device__ float g_sim_a[BQ * PP];
__device__ float g_bsum[16];

// ---------------- PTX helpers (legal on plain sm_100) ----------------
__device__ __forceinline__ uint32_t smem_u32(const void* p) {
    uint32_t a;
    asm("{ .reg .u64 t; cvta.to.shared.u64 t, %1; cvt.u32.u64 %0, t; }" : "=r"(a) : "l"(p));
    return a;
}
__device__ __forceinline__ void cp_async16(uint32_t dst, const void* src) {
    asm volatile("cp.async.cg.shared.global [%0], [%1], 16;" :: "r"(dst), "l"(src));
}
#define CP_COMMIT() asm volatile("cp.async.commit_group;" ::: "memory")
#define CP_WAIT2()  asm volatile("cp.async.wait_group 2;" ::: "memory")

__device__ __forceinline__ void ldsm_x4(uint32_t& r0, uint32_t& r1, uint32_t& r2,
                                        uint32_t& r3, uint32_t addr) {
    asm volatile("ldmatrix.sync.aligned.m8n8.x4.shared.b16 {%0,%1,%2,%3}, [%4];"
                 : "=r"(r0), "=r"(r1), "=r"(r2), "=r"(r3) : "r"(addr));
}
// FP8 e4m3 MMA, k=32, f16 accum (packed half2 x2). On Ada-lineage HW this
// runs at 2x the f32-accum rate; testing that hypothesis on this part.
__device__ __forceinline__ void mma16832_fp8_h(uint32_t& d0, uint32_t& d1,
                                               uint32_t a0, uint32_t a1, uint32_t a2, uint32_t a3,
                                               uint32_t b0, uint32_t b1) {
    asm volatile(
        "mma.sync.aligned.m16n8k32.row.col.f16.e4m3.e4m3.f16 "
        "{%0,%1}, {%2,%3,%4,%5}, {%6,%7}, {%0,%1};"
        : "+r"(d0), "+r"(d1)
        : "r"(a0), "r"(a1), "r"(a2), "r"(a3), "r"(b0), "r"(b1));
}

// 64B-row swizzle: 16B chunk c of row r -> slot c ^ ((r>>1)&3). Conflict-free
// for cp.async stores and every ldmatrix phase (validated R4-R12).
__device__ __forceinline__ uint32_t sw_off(uint32_t row, uint32_t c16) {
    return row * 64u + ((c16 ^ ((row >> 1) & 3u)) << 4);
}

// ---------------------------------------------------------------------------
// 1) L2-normalize all rows -> e4m3 g_keys
// ---------------------------------------------------------------------------
__global__ void __launch_bounds__(256) normalize_kernel(const float* __restrict__ q,
                                                        const float* __restrict__ d) {
    const int r = blockIdx.x;
    const float* src = (r < BQ) ? (q + (size_t)r * DD) : (d + (size_t)(r - BQ) * DD);
    __shared__ float sh[256];
    const int t = threadIdx.x;

    float4 v = make_float4(0.f, 0.f, 0.f, 0.f);
    float ss = 0.f;
    if (t < DD / 4) {
        v = ((const float4*)src)[t];
        ss = v.x * v.x + v.y * v.y + v.z * v.z + v.w * v.w;
    }
    sh[t] = ss; __syncthreads();
    #pragma unroll
    for (int s = 128; s > 0; s >>= 1) { if (t < s) sh[t] += sh[t + s]; __syncthreads(); }
    if (t < DD / 4) {
        float rn = 1.0f / fmaxf(sqrtf(sh[0]), 1e-12f);
        uint32_t o = 0;
        o |= (uint32_t)__nv_cvt_float_to_fp8(v.x * rn, __NV_SATFINITE, __NV_E4M3);
        o |= (uint32_t)__nv_cvt_float_to_fp8(v.y * rn, __NV_SATFINITE, __NV_E4M3) << 8;
        o |= (uint32_t)__nv_cvt_float_to_fp8(v.z * rn, __NV_SATFINITE, __NV_E4M3) << 16;
        o |= (uint32_t)__nv_cvt_float_to_fp8(v.w * rn, __NV_SATFINITE, __NV_E4M3) << 24;
        *(uint32_t*)&g_keys[(size_t)r * DD + t * 4] = o;
    }
}

// ---------------------------------------------------------------------------
// 2) FP8 MMA GEMM (f16 accum) + exp + rowsum. 128x128 tile, 8 warps, 64x32.
//    NPIPE=4 + single barrier per stage (R12 scheme).
//    Query-query diagonal contributes exactly zero (replaces "- exp(1/t)").
// ---------------------------------------------------------------------------
__device__ __forceinline__ void load_stage(uint32_t smem_base, int buf, int kt,
                                           int m0, int n0, int tid) {
    const uint32_t a_base = smem_base + SMEM_A(buf);
    const uint32_t b_base = smem_base + SMEM_B(buf);
    #pragma unroll
    for (int i = 0; i < 4; i++) {
        const int idx = tid + i * 256;          // 0..1023
        const int row = idx >> 2;               // 0..255 (0-127: A, 128-255: B)
        const int c   = idx & 3;                // 16B chunk within 64B row
        uint32_t dst;
        int gr;
        if (row < TILE_M) { gr = m0 + row;            dst = a_base + sw_off(row, c); }
        else              { gr = n0 + (row - TILE_M); dst = b_base + sw_off(row - TILE_M, c); }
        cp_async16(dst, g_keys + (size_t)gr * DD + kt + c * 16);
    }
}

__global__ void __launch_bounds__(256, 2) gemm_exp_kernel() {
    extern __shared__ char smem[];
    const uint32_t smem_base = smem_u32(smem);
    const int tid  = threadIdx.x;
    const int lane = tid & 31;
    const int wid  = tid >> 5;
    const int wm   = (wid & 1) * 64;         // warp M offset (2 rows of warps)
    const int wn   = (wid >> 1) * 32;        // warp N offset (4 cols of warps)
    const int ntile = blockIdx.x;            // 0..159
    const int mtile = blockIdx.y;            // 0..31
    const int m0 = mtile * TILE_M;
    const int n0 = ntile * TILE_N;

    uint32_t acc[4][4][2];                    // [mi][ni][d0,d1] packed half2
    #pragma unroll
    for (int i = 0; i < 4; i++)
        #pragma unroll
        for (int j = 0; j < 4; j++) { acc[i][j][0] = 0u; acc[i][j][1] = 0u; }

    // Prologue: 3 stages in flight
    load_stage(smem_base, 0, 0, m0, n0, tid);      CP_COMMIT();
    load_stage(smem_base, 1, KS, m0, n0, tid);     CP_COMMIT();
    load_stage(smem_base, 2, 2 * KS, m0, n0, tid); CP_COMMIT();

    const int lr = lane & 15;                // ldmatrix row-within-16
    const int lc = lane >> 4;                // ldmatrix 16B half select

    for (int s = 0; s < NSTAGES; s++) {
        const int buf = s & (NPIPE - 1);
        CP_WAIT2();                           // stage s data resident
        __syncthreads();                      // all warps past compute s-1

        if (s + 3 < NSTAGES) load_stage(smem_base, (s + 3) & (NPIPE - 1),
                                        (s + 3) * KS, m0, n0, tid);
        CP_COMMIT();

        const uint32_t a_base = smem_base + SMEM_A(buf);
        const uint32_t b_base = smem_base + SMEM_B(buf);

        #pragma unroll
        for (int ks = 0; ks < 2; ks++) {      // two k32 steps per 64-K stage
            const uint32_t c16 = ks * 2 + lc; // 16B chunk: k-halves 0-15 / 16-31
            uint32_t a[4][4];
            #pragma unroll
            for (int mi = 0; mi < 4; mi++) {
                const uint32_t row = wm + mi * 16 + lr;
                ldsm_x4(a[mi][0], a[mi][1], a[mi][2], a[mi][3], a_base + sw_off(row, c16));
            }
            uint32_t b[4][2];
            #pragma unroll
            for (int bp = 0; bp < 2; bp++) {  // each ldmatrix.x4 covers 16 n-rows
                const uint32_t row = wn + bp * 16 + lr;
                uint32_t q0, q1, q2, q3;
                ldsm_x4(q0, q1, q2, q3, b_base + sw_off(row, c16));
                b[bp * 2 + 0][0] = q0; b[bp * 2 + 0][1] = q2;   // n 0-7: k0-15, k16-31
                b[bp * 2 + 1][0] = q1; b[bp * 2 + 1][1] = q3;   // n 8-15
            }
            #pragma unroll
            for (int mi = 0; mi < 4; mi++)
                #pragma unroll
                for (int ni = 0; ni < 4; ni++)
                    mma16832_fp8_h(acc[mi][ni][0], acc[mi][ni][1],
                                   a[mi][0], a[mi][1], a[mi][2], a[mi][3],
                                   b[ni][0], b[ni][1]);
        }
    }

    // ---- Epilogue: unpack f16 accum, exp, row sums (diag excluded) ----
    const float INVT = (float)(1.0 / 0.07);
    float rs[4][2];                           // [mi][half: row / row+8]
    #pragma unroll
    for (int mi = 0; mi < 4; mi++) { rs[mi][0] = 0.f; rs[mi][1] = 0.f; }

    const int qr = lane >> 2;                 // quad row 0..7
    const int qc = (lane & 3) * 2;            // quad col base
    #pragma unroll
    for (int mi = 0; mi < 4; mi++) {
        const int r_lo = m0 + wm + mi * 16 + qr;
        const int r_hi = r_lo + 8;
        #pragma unroll
        for (int ni = 0; ni < 4; ni++) {
            const int cg = n0 + wn + ni * 8 + qc;   // global col of c0/c2
            float2 vlo = __half22float2(*(__half2*)&acc[mi][ni][0]); // row r_lo: c0,c1
            float2 vhi = __half22float2(*(__half2*)&acc[mi][ni][1]); // row r_hi: c2,c3
            float e0 = __expf(vlo.x * INVT);
            float e1 = __expf(vlo.y * INVT);
            float e2 = __expf(vhi.x * INVT);
            float e3 = __expf(vhi.y * INVT);
            // exclude query-query self-similarity (cg==row implies cg < BQ)
            if (cg     == r_lo) e0 = 0.f;
            if (cg + 1 == r_lo) e1 = 0.f;
            if (cg     == r_hi) e2 = 0.f;
            if (cg + 1 == r_hi) e3 = 0.f;
            rs[mi][0] += e0 + e1;
            rs[mi][1] += e2 + e3;
            const int kd0 = cg - BQ, kd1 = cg + 1 - BQ;
            if (kd0 >= 0 && (kd0 >> 2) == r_lo) g_sim_a[kd0] = e0;
            if (kd1 >= 0 && (kd1 >> 2) == r_lo) g_sim_a[kd1] = e1;
            if (kd0 >= 0 && (kd0 >> 2) == r_hi) g_sim_a[kd0] = e2;
            if (kd1 >= 0 && (kd1 >> 2) == r_hi) g_sim_a[kd1] = e3;
        }
    }
    // reduce across the 4 lanes of each quad-row
    #pragma unroll
    for (int mi = 0; mi < 4; mi++)
        #pragma unroll
        for (int h = 0; h < 2; h++) {
            rs[mi][h] += __shfl_xor_sync(0xffffffffu, rs[mi][h], 1);
            rs[mi][h] += __shfl_xor_sync(0xffffffffu, rs[mi][h], 2);
        }

    float* red = (float*)(smem + SMEM_RED);   // [4 warp_n][128 rows]
    __syncthreads();                          // stage buffers no longer needed
    if ((lane & 3) == 0) {
        const int wncol = wid >> 1;
        #pragma unroll
        for (int mi = 0; mi < 4; mi++)
            #pragma unroll
            for (int h = 0; h < 2; h++)
                red[wncol * 128 + wm + mi * 16 + h * 8 + qr] = rs[mi][h];
    }
    __syncthreads();
    if (tid < 128) {
        float s = red[tid] + red[128 + tid] + red[256 + tid] + red[384 + tid];
        g_partial[ntile * BQ + m0 + tid] = s;
    }
}

// ---------------------------------------------------------------------------
// 3) Fused rowsum + log-loss partials. 16 blocks x 256 threads, 1 row/thread.
// ---------------------------------------------------------------------------
__global__ void __launch_bounds__(256) loss_partial_kernel() {
    __shared__ float sh[256];
    const int tid = threadIdx.x;
    const int i = blockIdx.x * 256 + tid;     // 0..4095
    float s = 0.f;
    #pragma unroll 4
    for (int t = 0; t < NTILES; t++) s += g_partial[t * BQ + i];
    const float a0 = g_sim_a[4 * i + 0];
    const float a1 = g_sim_a[4 * i + 1];
    const float a2 = g_sim_a[4 * i + 2];
    const float a3 = g_sim_a[4 * i + 3];
    const float R = s - (a0 + a1 + a2 + a3);  // rowsum already excludes self term
    float local = (logf(R + a0) - logf(a0)) + (logf(R + a1) - logf(a1))
                + (logf(R + a2) - logf(a2)) + (logf(R + a3) - logf(a3));
    sh[tid] = local; __syncthreads();
    #pragma unroll
    for (int s2 = 128; s2 > 0; s2 >>= 1) { if (tid < s2) sh[tid] += sh[tid + s2]; __syncthreads(); }
    if (tid == 0) g_bsum[blockIdx.x] = sh[0];
}

__global__ void loss_final_kernel(float* __restrict__ out) {
    if (threadIdx.x == 0) {
        float s = 0.f;
        #pragma unroll
        for (int b = 0; b < 16; b++) s += g_bsum[b];
        out[0] = s * (1.0f / (float)(BQ * PP));
    }
}

// ---------------------------------------------------------------------------
extern "C" void kernel_launch(void* const* d_in, const int* in_sizes, int n_in,
                              void* d_out, int out_size) {
    const float* q = (const float*)d_in[0];   // [4096, 768]
    const float* d = (const float*)d_in[1];   // [16384, 768]
    float* out = (float*)d_out;

    cudaFuncSetAttribute(gemm_exp_kernel,
                         cudaFuncAttributeMaxDynamicSharedMemorySize, SMEM_TOTAL);

    normalize_kernel<<<NKEYS, 256>>>(q, d);
    gemm_exp_kernel<<<dim3(NTILES, MTILES), 256, SMEM_TOTAL>>>();
    loss_partial_kernel<<<16, 256>>>();
    loss_final_kernel<<<1, 32>>>(out);
}